// round 16
// baseline (speedup 1.0000x reference)
#include <cuda_runtime.h>
#include <cuda_fp16.h>

#define NTOK  32768
#define DIM   512
#define MCODE 2048
#define NORTH 128

static __device__ float              g_xnorm[NTOK];
static __device__ float              g_enorm[MCODE];
static __device__ unsigned long long g_key[NTOK];
static __device__ float              g_counts[MCODE];
static __device__ float              g_dw[MCODE * DIM];
static __device__ float              g_newemb[MCODE * DIM];
static __device__ float              g_tokloss[NTOK];
static __device__ double             g_scal[2];
static __device__ float              g_newcount[MCODE];
static __device__ int                g_sel[NORTH];
static __device__ float              g_valid[NORTH];
static __device__ float              g_nvalid;
static __device__ float              g_normed[NORTH * DIM];
static __device__ __half             g_xh[NTOK * DIM];
static __device__ __half             g_xl[NTOK * DIM];
static __device__ __half             g_eh[MCODE * DIM];   // emb * 4096, hi
static __device__ __half             g_el[MCODE * DIM];   // emb * 4096, lo

#define O_QUANT   ((size_t)0)
#define O_COMMIT  ((size_t)16777216)
#define O_CODEBK  ((size_t)16777217)
#define O_ORTHO   ((size_t)16777218)
#define O_IDX     ((size_t)16777219)
#define O_NEWEMB  ((size_t)16809987)
#define O_NEWCNT  ((size_t)17858563)
#define O_NEWW    ((size_t)17860611)

__device__ __forceinline__ unsigned smem_u32(const void* p) {
    unsigned a;
    asm("{ .reg .u64 t; cvta.to.shared.u64 t, %1; cvt.u32.u64 %0, t; }"
        : "=r"(a) : "l"(p));
    return a;
}
__device__ __forceinline__ void ldmx4(unsigned r[4], unsigned addr) {
    asm volatile("ldmatrix.sync.aligned.m8n8.x4.shared.b16 {%0,%1,%2,%3},[%4];"
                 : "=r"(r[0]), "=r"(r[1]), "=r"(r[2]), "=r"(r[3]) : "r"(addr));
}
__device__ __forceinline__ void mma16816(float c[4], const unsigned a[4],
                                         unsigned b0, unsigned b1) {
    asm volatile(
        "mma.sync.aligned.m16n8k16.row.col.f32.f16.f16.f32 "
        "{%0,%1,%2,%3},{%4,%5,%6,%7},{%8,%9},{%0,%1,%2,%3};"
        : "+f"(c[0]), "+f"(c[1]), "+f"(c[2]), "+f"(c[3])
        : "r"(a[0]), "r"(a[1]), "r"(a[2]), "r"(a[3]), "r"(b0), "r"(b1));
}
__device__ __forceinline__ void cpasync16(unsigned dst, const void* src) {
    asm volatile("cp.async.cg.shared.global [%0], [%1], 16;"
                 :: "r"(dst), "l"(src));
}
// packed f32x2 -> f16x2 RN convert; lower = a, upper = b (bit-identical per
// element to __float2half_rn)
__device__ __forceinline__ unsigned f2h2(float a, float b) {
    unsigned r;
    asm("cvt.rn.f16x2.f32 %0, %1, %2;" : "=r"(r) : "f"(b), "f"(a));
    return r;
}

// fused: row L2-norm + fp16 two-way split + ALL scratch zeroing.
// Packed f16x2 converts + STG.64 stores (values bit-identical to scalar path).
__global__ void k_prep(const float* __restrict__ x, const float* __restrict__ emb) {
    const int gt = blockIdx.x * blockDim.x + threadIdx.x;   // 0 .. 1114111
    if (gt < MCODE * DIM)   g_dw[gt] = 0.f;
    if (gt < NTOK)          g_key[gt] = 0xFFFFFFFFFFFFFFFFULL;
    if (gt < MCODE)         g_counts[gt] = 0.f;
    if (gt == 0) { g_scal[0] = 0.0; g_scal[1] = 0.0; }

    int w    = gt >> 5;
    int lane = threadIdx.x & 31;
    if (w >= NTOK + MCODE) return;
    const bool isx = (w < NTOK);
    const int  row = isx ? w : (w - NTOK);
    const float4* s4 = (const float4*)((isx ? x : emb) + (size_t)row * DIM);
    const float sc = isx ? 1.0f : 4096.0f;
    __half2* hd = (__half2*)((isx ? g_xh : g_eh) + (size_t)row * DIM);
    __half2* ld = (__half2*)((isx ? g_xl : g_el) + (size_t)row * DIM);
    double acc = 0.0;
#pragma unroll
    for (int i = 0; i < 4; i++) {
        float4 v = s4[lane + i * 32];
        acc += (double)v.x * v.x + (double)v.y * v.y + (double)v.z * v.z + (double)v.w * v.w;
        const float f0 = v.x * sc, f1 = v.y * sc, f2 = v.z * sc, f3 = v.w * sc;
        const unsigned hp0 = f2h2(f0, f1);
        const unsigned hp1 = f2h2(f2, f3);
        const float2 g01 = __half22float2(*(const __half2*)&hp0);
        const float2 g23 = __half22float2(*(const __half2*)&hp1);
        const unsigned lp0 = f2h2(f0 - g01.x, f1 - g01.y);
        const unsigned lp1 = f2h2(f2 - g23.x, f3 - g23.y);
        *(uint2*)(hd + 2 * (lane + i * 32)) = make_uint2(hp0, hp1);
        *(uint2*)(ld + 2 * (lane + i * 32)) = make_uint2(lp0, lp1);
    }
    for (int off = 16; off; off >>= 1) acc += __shfl_down_sync(0xffffffffu, acc, off);
    if (lane == 0) {
        if (isx) g_xnorm[row] = (float)acc; else g_enorm[row] = (float)acc;
    }
}

__global__ void k_pad() {}

// ---- HMMA distance GEMM + fused argmin (FROZEN) -------------------------------
// 2 CTAs/SM: 256 threads (8 warps, 4M x 2N, warp tile 32x64), CTA tile 128x128,
// K chunks of 32 (16 chunks), PITCH 80, 2-stage cp.async.
// FROZEN INVARIANT: per-element accumulation order = k16-block ascending ->
// pass {xh*el, xl*eh, xh*eh}. Do not reorder HMMAs (R11 regression).
#define PITCH  80
#define T_T    (128 * PITCH)            // 10240 B per tile
#define STAGEB (4 * T_T)                // 40960 B

__global__ __launch_bounds__(256, 2)
void k_mma() {
    extern __shared__ char sm[];
    const unsigned sb = smem_u32(sm);
    const int tid = threadIdx.x;
    const int warp = tid >> 5, lane = tid & 31;
    const int wm = warp & 3, wn = warp >> 2;     // 4 x 2 warp grid
    const int row0 = blockIdx.y * 128;
    const int col0 = blockIdx.x * 128;

    float C[2][8][4];
#pragma unroll
    for (int i = 0; i < 2; i++)
#pragma unroll
        for (int j = 0; j < 8; j++)
#pragma unroll
            for (int u = 0; u < 4; u++) C[i][j][u] = 0.f;

    auto load_chunk = [&](int c, int buf) {
        const int kc = c * 32;
        const unsigned dstb = sb + buf * STAGEB;
#pragma unroll
        for (int i = 0; i < 8; i++) {
            const int u = i * 256 + tid;
            const int tl = u >> 9, rem = u & 511;
            const int row = rem >> 2, cu = rem & 3;
            const __half* src = (tl == 0) ? g_xh + (size_t)(row0 + row) * DIM
                              : (tl == 1) ? g_xl + (size_t)(row0 + row) * DIM
                              : (tl == 2) ? g_eh + (size_t)(col0 + row) * DIM
                                          : g_el + (size_t)(col0 + row) * DIM;
            cpasync16(dstb + tl * T_T + row * PITCH + cu * 16, src + kc + cu * 8);
        }
        asm volatile("cp.async.commit_group;");
    };

    auto compute = [&](int buf) {
        const unsigned base = sb + buf * STAGEB;
        const unsigned Axh = base + (wm * 32 + (lane & 15)) * PITCH;
        const unsigned Axl = Axh + T_T;
        const unsigned Beh = base + 2 * T_T + (wn * 64 + (lane & 15)) * PITCH;
        const unsigned Bel = Beh + T_T;
#pragma unroll
        for (int s = 0; s < 2; s++) {
            const unsigned coff = s * 32 + (lane >> 4) * 16;
            unsigned ah0[4], ah1[4], al0[4], al1[4], bh[4][4], bl[4][4];
            ldmx4(ah0, Axh + coff);
            ldmx4(ah1, Axh + 16 * PITCH + coff);
#pragma unroll
            for (int nb = 0; nb < 4; nb++) ldmx4(bl[nb], Bel + nb * 16 * PITCH + coff);
            ldmx4(al0, Axl + coff);
            ldmx4(al1, Axl + 16 * PITCH + coff);
#pragma unroll
            for (int nb = 0; nb < 4; nb++) ldmx4(bh[nb], Beh + nb * 16 * PITCH + coff);
            // pass 0: xh * el
#pragma unroll
            for (int nt = 0; nt < 8; nt++) {
                const int nb = nt >> 1, hi = nt & 1;
                mma16816(C[0][nt], ah0, bl[nb][hi], bl[nb][hi + 2]);
                mma16816(C[1][nt], ah1, bl[nb][hi], bl[nb][hi + 2]);
            }
            // pass 1: xl * eh
#pragma unroll
            for (int nt = 0; nt < 8; nt++) {
                const int nb = nt >> 1, hi = nt & 1;
                mma16816(C[0][nt], al0, bh[nb][hi], bh[nb][hi + 2]);
                mma16816(C[1][nt], al1, bh[nb][hi], bh[nb][hi + 2]);
            }
            // pass 2: xh * eh
#pragma unroll
            for (int nt = 0; nt < 8; nt++) {
                const int nb = nt >> 1, hi = nt & 1;
                mma16816(C[0][nt], ah0, bh[nb][hi], bh[nb][hi + 2]);
                mma16816(C[1][nt], ah1, bh[nb][hi], bh[nb][hi + 2]);
            }
        }
    };

    load_chunk(0, 0);
#pragma unroll 1
    for (int c = 0; c < 16; c++) {
        asm volatile("cp.async.wait_group 0;");
        __syncthreads();
        if (c + 1 < 16) load_chunk(c + 1, (c + 1) & 1);
        compute(c & 1);
    }

    // epilogue: d = fl((xn+en) - 2*dot), dot = C * 2^-12 (exact scale in fmaf)
    const int qr = lane >> 2, qc = lane & 3;
    float env[16];
#pragma unroll
    for (int nt = 0; nt < 8; nt++) {
#pragma unroll
        for (int h = 0; h < 2; h++)
            env[nt * 2 + h] = g_enorm[col0 + wn * 64 + nt * 8 + qc * 2 + h];
    }
#pragma unroll
    for (int mt = 0; mt < 2; mt++) {
#pragma unroll
        for (int hf = 0; hf < 2; hf++) {
            const int row = row0 + wm * 32 + mt * 16 + hf * 8 + qr;
            const float xn = g_xnorm[row];
            float mv = __int_as_float(0x7f800000);
            int   mi = 0;
#pragma unroll
            for (int nt = 0; nt < 8; nt++) {
#pragma unroll
                for (int h = 0; h < 2; h++) {
                    float d = fmaf(-0x1p-11f, C[mt][nt][hf * 2 + h],
                                   xn + env[nt * 2 + h]);
                    int coln = col0 + wn * 64 + nt * 8 + qc * 2 + h;
                    if (d < mv) { mv = d; mi = coln; }
                }
            }
#pragma unroll
            for (int off = 2; off; off >>= 1) {
                float ov = __shfl_down_sync(0xffffffffu, mv, off, 4);
                int   oi = __shfl_down_sync(0xffffffffu, mi, off, 4);
                if (ov < mv || (ov == mv && oi < mi)) { mv = ov; mi = oi; }
            }
            if (qc == 0) {
                unsigned fb = __float_as_uint(mv);
                fb = (fb & 0x80000000u) ? ~fb : (fb | 0x80000000u);
                unsigned long long key =
                    ((unsigned long long)fb << 32) | (unsigned)mi;
                atomicMin(&g_key[row], key);
            }
        }
    }
}

// per-token epilogue: quant_st, per-token loss store, counts, dw scatter
__global__ void k_token(const float* __restrict__ x, const float* __restrict__ emb,
                        float* __restrict__ out) {
    const int t = blockIdx.x;
    const int tid = threadIdx.x;
    const int idx = (int)(g_key[t] & 0xFFFFFFFFULL);
    float4 xv = *(const float4*)(x   + (size_t)t   * DIM + tid * 4);
    float4 qv = *(const float4*)(emb + (size_t)idx * DIM + tid * 4);
    float4 o;
    o.x = xv.x + (qv.x - xv.x);
    o.y = xv.y + (qv.y - xv.y);
    o.z = xv.z + (qv.z - xv.z);
    o.w = xv.w + (qv.w - xv.w);
    *(float4*)(out + O_QUANT + (size_t)t * DIM + tid * 4) = o;
    float ex = xv.x - qv.x, ey = xv.y - qv.y, ez = xv.z - qv.z, ew = xv.w - qv.w;
    float ls = ex * ex + ey * ey + ez * ez + ew * ew;
    float* dwp = g_dw + (size_t)idx * DIM + tid * 4;
    asm volatile("red.global.add.v4.f32 [%0], {%1,%2,%3,%4};"
                 :: "l"(dwp), "f"(xv.x), "f"(xv.y), "f"(xv.z), "f"(xv.w) : "memory");
    for (int off = 16; off; off >>= 1) ls += __shfl_down_sync(0xffffffffu, ls, off);
    __shared__ float ws[4];
    if ((tid & 31) == 0) ws[tid >> 5] = ls;
    __syncthreads();
    if (tid == 0) {
        g_tokloss[t] = ws[0] + ws[1] + ws[2] + ws[3];
        atomicAdd(&g_counts[idx], 1.0f);
        out[O_IDX + t] = (float)idx;
    }
}

__global__ void k_stats(const float* __restrict__ ema_count, float* __restrict__ out) {
    const int t = threadIdx.x;
    const int c0 = 2 * t, c1 = 2 * t + 1;
    const int lane = t & 31, wid = t >> 5;
    float cnt0 = g_counts[c0], cnt1 = g_counts[c1];
    float raw0 = 0.999f * ema_count[c0] + 0.001f * cnt0;
    float raw1 = 0.999f * ema_count[c1] + 0.001f * cnt1;

    // deterministic loss reduction: 32 contiguous partials per thread
    double lsum = 0.0;
#pragma unroll 4
    for (int i = 0; i < 32; i++) lsum += (double)g_tokloss[t * 32 + i];

    double nl = (double)raw0 + (double)raw1;
    for (int off = 16; off; off >>= 1) {
        nl   += __shfl_down_sync(0xffffffffu, nl, off);
        lsum += __shfl_down_sync(0xffffffffu, lsum, off);
    }
    __shared__ double wn[32], wl[32];
    __shared__ float s_n;
    if (lane == 0) { wn[wid] = nl; wl[wid] = lsum; }
    __syncthreads();
    if (t == 0) {
        double s = 0, l = 0;
        for (int i = 0; i < 32; i++) { s += wn[i]; l += wl[i]; }
        s_n = (float)s;
        double m = l * (1.0 / 16777216.0);
        out[O_CODEBK] = (float)m;
        out[O_COMMIT] = (float)(0.25 * m);
    }
    __syncthreads();
    const float n = s_n;
    const float denom = n + 0.02048f;
    float nc0 = ((raw0 + 1e-5f) / denom) * n;
    float nc1 = ((raw1 + 1e-5f) / denom) * n;
    g_newcount[c0] = nc0; g_newcount[c1] = nc1;
    out[O_NEWCNT + c0] = nc0; out[O_NEWCNT + c1] = nc1;

    int f0 = cnt0 > 0.f ? 1 : 0, f1 = cnt1 > 0.f ? 1 : 0;
    int v = f0 + f1;
    int inc = v;
    for (int off = 1; off < 32; off <<= 1) {
        int o = __shfl_up_sync(0xffffffffu, inc, off);
        if (lane >= off) inc += o;
    }
    __shared__ int wsum[32];
    if (lane == 31) wsum[wid] = inc;
    __syncthreads();
    if (wid == 0) {
        int w = wsum[lane];
        for (int off = 1; off < 32; off <<= 1) {
            int o = __shfl_up_sync(0xffffffffu, w, off);
            if (lane >= off) w += o;
        }
        wsum[lane] = w;
    }
    __syncthreads();
    const int total_used = wsum[31];
    int base = (wid > 0 ? wsum[wid - 1] : 0) + (inc - v);
    int p0 = f0 ? base : total_used + (c0 - base);
    int eU1 = base + f0;
    int p1 = f1 ? eU1 : total_used + (c1 - eU1);
    if (p0 < NORTH) { g_sel[p0] = c0; g_valid[p0] = f0 ? 1.0f : 0.0f; }
    if (p1 < NORTH) { g_sel[p1] = c1; g_valid[p1] = f1 ? 1.0f : 0.0f; }
    if (t == 0) {
        g_nvalid = (float)(total_used < NORTH ? total_used : NORTH);
    }
}

__global__ void k_weight(const float* __restrict__ ema_weight, float* __restrict__ out) {
    const int row = blockIdx.x;
    const int tid = threadIdx.x;
    const float nc = g_newcount[row];
    const size_t off = (size_t)row * DIM + tid * 4;
    float4 w  = *(const float4*)(ema_weight + off);
    float4 dv = *(const float4*)(g_dw + off);
    float nw[4], ne[4];
    nw[0] = 0.999f * w.x + 0.001f * dv.x;
    nw[1] = 0.999f * w.y + 0.001f * dv.y;
    nw[2] = 0.999f * w.z + 0.001f * dv.z;
    nw[3] = 0.999f * w.w + 0.001f * dv.w;
#pragma unroll
    for (int u = 0; u < 4; u++) ne[u] = nw[u] / nc;
#pragma unroll
    for (int u = 0; u < 4; u++) {
        out[O_NEWW + off + u]   = nw[u];
        out[O_NEWEMB + off + u] = ne[u];
    }
    *(float4*)(g_newemb + off) = make_float4(ne[0], ne[1], ne[2], ne[3]);
}

__global__ void k_normed() {
    const int r = blockIdx.x;
    const int tid = threadIdx.x;
    const int j = g_sel[r];
    const float valid = g_valid[r];
    float4 v = *(const float4*)(g_newemb + (size_t)j * DIM + tid * 4);
    float ss = v.x * v.x + v.y * v.y + v.z * v.z + v.w * v.w;
    for (int off = 16; off; off >>= 1) ss += __shfl_down_sync(0xffffffffu, ss, off);
    __shared__ float ws[4];
    __shared__ float s_norm;
    if ((tid & 31) == 0) ws[tid >> 5] = ss;
    __syncthreads();
    if (tid == 0) s_norm = fmaxf(sqrtf(ws[0] + ws[1] + ws[2] + ws[3]), 1e-12f);
    __syncthreads();
    const float nrm = s_norm;
    float4 o;
    o.x = v.x / nrm * valid; o.y = v.y / nrm * valid;
    o.z = v.z / nrm * valid; o.w = v.w / nrm * valid;
    *(float4*)(g_normed + (size_t)r * DIM + tid * 4) = o;
}

__global__ void k_cos() {
    const int a = blockIdx.x;
    const int b = threadIdx.x;
    __shared__ float4 sa[128];
    sa[b] = ((const float4*)(g_normed + (size_t)a * DIM))[b];
    __syncthreads();
    const float4* vb = (const float4*)(g_normed + (size_t)b * DIM);
    float dot = 0.f;
#pragma unroll 8
    for (int i = 0; i < 128; i++) {
        float4 pa = sa[i], pb = vb[i];
        dot += pa.x * pb.x + pa.y * pb.y + pa.z * pb.z + pa.w * pb.w;
    }
    float diag = (a == b) ? g_valid[a] : 0.f;
    float d = dot - diag;
    float sq = d * d;
    for (int off = 16; off; off >>= 1) sq += __shfl_down_sync(0xffffffffu, sq, off);
    __shared__ float ws[4];
    if ((b & 31) == 0) ws[b >> 5] = sq;
    __syncthreads();
    if (b == 0) atomicAdd(&g_scal[1], (double)(ws[0] + ws[1] + ws[2] + ws[3]));
}

__global__ void k_ortho(float* __restrict__ out) {
    float nv = g_nvalid;
    out[O_ORTHO] = (float)(g_scal[1] / ((double)nv * (double)nv) * 10.0);
}

extern "C" void kernel_launch(void* const* d_in, const int* in_sizes, int n_in,
                              void* d_out, int out_size) {
    const float* x          = (const float*)d_in[0];
    const float* emb        = (const float*)d_in[1];
    const float* ema_count  = (const float*)d_in[2];
    const float* ema_weight = (const float*)d_in[3];
    float* out = (float*)d_out;

    cudaFuncSetAttribute(k_mma, cudaFuncAttributeMaxDynamicSharedMemorySize,
                         2 * STAGEB);

    k_pad<<<1, 32>>>();                           // #1
    k_pad<<<1, 32>>>();                           // #2
    k_pad<<<1, 32>>>();                           // #3
    k_prep<<<4352, 256>>>(x, emb);                // #4 (profiled this round)
    k_mma<<<dim3(16, 256), 256, 2 * STAGEB>>>();
    k_token<<<NTOK, 128>>>(x, emb, out);
    k_stats<<<1, 1024>>>(ema_count, out);
    k_weight<<<MCODE, 128>>>(ema_weight, out);
    k_normed<<<NORTH, 128>>>();
    k_cos<<<NORTH, 128>>>();
    k_ortho<<<1, 1>>>(out);
}

// round 17
// speedup vs baseline: 1.0994x; 1.0994x over previous
#include <cuda_runtime.h>
#include <cuda_fp16.h>

#define NTOK  32768
#define DIM   512
#define MCODE 2048
#define NORTH 128

static __device__ float              g_xnorm[NTOK];
static __device__ float              g_enorm[MCODE];
static __device__ unsigned long long g_key[NTOK];
static __device__ float              g_counts[MCODE];
static __device__ float              g_dw[MCODE * DIM];
static __device__ float              g_newemb[MCODE * DIM];
static __device__ float              g_tokloss[NTOK];
static __device__ double             g_scal[2];
static __device__ float              g_newcount[MCODE];
static __device__ int                g_sel[NORTH];
static __device__ float              g_valid[NORTH];
static __device__ float              g_nvalid;
static __device__ float              g_normed[NORTH * DIM];
static __device__ __half             g_xh[NTOK * DIM];
static __device__ __half             g_xl[NTOK * DIM];
static __device__ __half             g_eh[MCODE * DIM];   // emb * 4096, hi
static __device__ __half             g_el[MCODE * DIM];   // emb * 4096, lo

#define O_QUANT   ((size_t)0)
#define O_COMMIT  ((size_t)16777216)
#define O_CODEBK  ((size_t)16777217)
#define O_ORTHO   ((size_t)16777218)
#define O_IDX     ((size_t)16777219)
#define O_NEWEMB  ((size_t)16809987)
#define O_NEWCNT  ((size_t)17858563)
#define O_NEWW    ((size_t)17860611)

__device__ __forceinline__ unsigned smem_u32(const void* p) {
    unsigned a;
    asm("{ .reg .u64 t; cvta.to.shared.u64 t, %1; cvt.u32.u64 %0, t; }"
        : "=r"(a) : "l"(p));
    return a;
}
__device__ __forceinline__ void ldmx4(unsigned r[4], unsigned addr) {
    asm volatile("ldmatrix.sync.aligned.m8n8.x4.shared.b16 {%0,%1,%2,%3},[%4];"
                 : "=r"(r[0]), "=r"(r[1]), "=r"(r[2]), "=r"(r[3]) : "r"(addr));
}
__device__ __forceinline__ void mma16816(float c[4], const unsigned a[4],
                                         unsigned b0, unsigned b1) {
    asm volatile(
        "mma.sync.aligned.m16n8k16.row.col.f32.f16.f16.f32 "
        "{%0,%1,%2,%3},{%4,%5,%6,%7},{%8,%9},{%0,%1,%2,%3};"
        : "+f"(c[0]), "+f"(c[1]), "+f"(c[2]), "+f"(c[3])
        : "r"(a[0]), "r"(a[1]), "r"(a[2]), "r"(a[3]), "r"(b0), "r"(b1));
}
__device__ __forceinline__ void cpasync16(unsigned dst, const void* src) {
    asm volatile("cp.async.cg.shared.global [%0], [%1], 16;"
                 :: "r"(dst), "l"(src));
}
// packed f32x2 -> f16x2 RN convert; lower = a, upper = b
__device__ __forceinline__ unsigned f2h2(float a, float b) {
    unsigned r;
    asm("cvt.rn.f16x2.f32 %0, %1, %2;" : "=r"(r) : "f"(b), "f"(a));
    return r;
}
// error-free accumulate s (+ exact square residual e) into df64 (hi, lo).
// Intrinsics prevent FMA contraction, which would break TwoSum exactness.
__device__ __forceinline__ void df64_acc_sq(float v, float& hi, float& lo) {
    float s = __fmul_rn(v, v);
    float e = fmaf(v, v, -s);                 // exact residual of the square
    float t = __fadd_rn(hi, s);
    float b = __fsub_rn(t, hi);
    float err = __fadd_rn(__fsub_rn(hi, __fsub_rn(t, b)), __fsub_rn(s, b));
    hi = t;
    lo = __fadd_rn(lo, __fadd_rn(err, e));
}
__device__ __forceinline__ void df64_add(float ohi, float olo, float& hi, float& lo) {
    float t = __fadd_rn(hi, ohi);
    float b = __fsub_rn(t, hi);
    float err = __fadd_rn(__fsub_rn(hi, __fsub_rn(t, b)), __fsub_rn(ohi, b));
    hi = t;
    lo = __fadd_rn(lo, __fadd_rn(olo, err));
}

// fused: row L2-norm (df64 — no fp64 pipe) + fp16 split + scratch zeroing
__global__ void k_prep(const float* __restrict__ x, const float* __restrict__ emb) {
    const int gt = blockIdx.x * blockDim.x + threadIdx.x;   // 0 .. 1114111
    if (gt < MCODE * DIM)   g_dw[gt] = 0.f;
    if (gt < NTOK)          g_key[gt] = 0xFFFFFFFFFFFFFFFFULL;
    if (gt < MCODE)         g_counts[gt] = 0.f;
    if (gt == 0) { g_scal[0] = 0.0; g_scal[1] = 0.0; }

    int w    = gt >> 5;
    int lane = threadIdx.x & 31;
    if (w >= NTOK + MCODE) return;
    const bool isx = (w < NTOK);
    const int  row = isx ? w : (w - NTOK);
    const float4* s4 = (const float4*)((isx ? x : emb) + (size_t)row * DIM);
    const float sc = isx ? 1.0f : 4096.0f;
    __half2* hd = (__half2*)((isx ? g_xh : g_eh) + (size_t)row * DIM);
    __half2* ld = (__half2*)((isx ? g_xl : g_el) + (size_t)row * DIM);
    float hi = 0.f, lo = 0.f;
#pragma unroll
    for (int i = 0; i < 4; i++) {
        float4 v = s4[lane + i * 32];
        df64_acc_sq(v.x, hi, lo);
        df64_acc_sq(v.y, hi, lo);
        df64_acc_sq(v.z, hi, lo);
        df64_acc_sq(v.w, hi, lo);
        const float f0 = v.x * sc, f1 = v.y * sc, f2 = v.z * sc, f3 = v.w * sc;
        const unsigned hp0 = f2h2(f0, f1);
        const unsigned hp1 = f2h2(f2, f3);
        const float2 g01 = __half22float2(*(const __half2*)&hp0);
        const float2 g23 = __half22float2(*(const __half2*)&hp1);
        const unsigned lp0 = f2h2(f0 - g01.x, f1 - g01.y);
        const unsigned lp1 = f2h2(f2 - g23.x, f3 - g23.y);
        *(uint2*)(hd + 2 * (lane + i * 32)) = make_uint2(hp0, hp1);
        *(uint2*)(ld + 2 * (lane + i * 32)) = make_uint2(lp0, lp1);
    }
    for (int off = 16; off; off >>= 1) {
        float ohi = __shfl_down_sync(0xffffffffu, hi, off);
        float olo = __shfl_down_sync(0xffffffffu, lo, off);
        df64_add(ohi, olo, hi, lo);
    }
    if (lane == 0) {
        float r = __fadd_rn(hi, lo);
        if (isx) g_xnorm[row] = r; else g_enorm[row] = r;
    }
}

__global__ void k_pad() {}

// ---- HMMA distance GEMM + fused argmin (FROZEN) -------------------------------
// 2 CTAs/SM: 256 threads (8 warps, 4M x 2N, warp tile 32x64), CTA tile 128x128,
// K chunks of 32 (16 chunks), PITCH 80, 2-stage cp.async.
// FROZEN INVARIANT: per-element accumulation order = k16-block ascending ->
// pass {xh*el, xl*eh, xh*eh}. Do not reorder HMMAs (R11 regression).
#define PITCH  80
#define T_T    (128 * PITCH)            // 10240 B per tile
#define STAGEB (4 * T_T)                // 40960 B

__global__ __launch_bounds__(256, 2)
void k_mma() {
    extern __shared__ char sm[];
    const unsigned sb = smem_u32(sm);
    const int tid = threadIdx.x;
    const int warp = tid >> 5, lane = tid & 31;
    const int wm = warp & 3, wn = warp >> 2;     // 4 x 2 warp grid
    const int row0 = blockIdx.y * 128;
    const int col0 = blockIdx.x * 128;

    float C[2][8][4];
#pragma unroll
    for (int i = 0; i < 2; i++)
#pragma unroll
        for (int j = 0; j < 8; j++)
#pragma unroll
            for (int u = 0; u < 4; u++) C[i][j][u] = 0.f;

    auto load_chunk = [&](int c, int buf) {
        const int kc = c * 32;
        const unsigned dstb = sb + buf * STAGEB;
#pragma unroll
        for (int i = 0; i < 8; i++) {
            const int u = i * 256 + tid;
            const int tl = u >> 9, rem = u & 511;
            const int row = rem >> 2, cu = rem & 3;
            const __half* src = (tl == 0) ? g_xh + (size_t)(row0 + row) * DIM
                              : (tl == 1) ? g_xl + (size_t)(row0 + row) * DIM
                              : (tl == 2) ? g_eh + (size_t)(col0 + row) * DIM
                                          : g_el + (size_t)(col0 + row) * DIM;
            cpasync16(dstb + tl * T_T + row * PITCH + cu * 16, src + kc + cu * 8);
        }
        asm volatile("cp.async.commit_group;");
    };

    auto compute = [&](int buf) {
        const unsigned base = sb + buf * STAGEB;
        const unsigned Axh = base + (wm * 32 + (lane & 15)) * PITCH;
        const unsigned Axl = Axh + T_T;
        const unsigned Beh = base + 2 * T_T + (wn * 64 + (lane & 15)) * PITCH;
        const unsigned Bel = Beh + T_T;
#pragma unroll
        for (int s = 0; s < 2; s++) {
            const unsigned coff = s * 32 + (lane >> 4) * 16;
            unsigned ah0[4], ah1[4], al0[4], al1[4], bh[4][4], bl[4][4];
            ldmx4(ah0, Axh + coff);
            ldmx4(ah1, Axh + 16 * PITCH + coff);
#pragma unroll
            for (int nb = 0; nb < 4; nb++) ldmx4(bl[nb], Bel + nb * 16 * PITCH + coff);
            ldmx4(al0, Axl + coff);
            ldmx4(al1, Axl + 16 * PITCH + coff);
#pragma unroll
            for (int nb = 0; nb < 4; nb++) ldmx4(bh[nb], Beh + nb * 16 * PITCH + coff);
            // pass 0: xh * el
#pragma unroll
            for (int nt = 0; nt < 8; nt++) {
                const int nb = nt >> 1, hi = nt & 1;
                mma16816(C[0][nt], ah0, bl[nb][hi], bl[nb][hi + 2]);
                mma16816(C[1][nt], ah1, bl[nb][hi], bl[nb][hi + 2]);
            }
            // pass 1: xl * eh
#pragma unroll
            for (int nt = 0; nt < 8; nt++) {
                const int nb = nt >> 1, hi = nt & 1;
                mma16816(C[0][nt], al0, bh[nb][hi], bh[nb][hi + 2]);
                mma16816(C[1][nt], al1, bh[nb][hi], bh[nb][hi + 2]);
            }
            // pass 2: xh * eh
#pragma unroll
            for (int nt = 0; nt < 8; nt++) {
                const int nb = nt >> 1, hi = nt & 1;
                mma16816(C[0][nt], ah0, bh[nb][hi], bh[nb][hi + 2]);
                mma16816(C[1][nt], ah1, bh[nb][hi], bh[nb][hi + 2]);
            }
        }
    };

    load_chunk(0, 0);
#pragma unroll 1
    for (int c = 0; c < 16; c++) {
        asm volatile("cp.async.wait_group 0;");
        __syncthreads();
        if (c + 1 < 16) load_chunk(c + 1, (c + 1) & 1);
        compute(c & 1);
    }

    // epilogue: d = fl((xn+en) - 2*dot), dot = C * 2^-12 (exact scale in fmaf)
    const int qr = lane >> 2, qc = lane & 3;
    float env[16];
#pragma unroll
    for (int nt = 0; nt < 8; nt++) {
#pragma unroll
        for (int h = 0; h < 2; h++)
            env[nt * 2 + h] = g_enorm[col0 + wn * 64 + nt * 8 + qc * 2 + h];
    }
#pragma unroll
    for (int mt = 0; mt < 2; mt++) {
#pragma unroll
        for (int hf = 0; hf < 2; hf++) {
            const int row = row0 + wm * 32 + mt * 16 + hf * 8 + qr;
            const float xn = g_xnorm[row];
            float mv = __int_as_float(0x7f800000);
            int   mi = 0;
#pragma unroll
            for (int nt = 0; nt < 8; nt++) {
#pragma unroll
                for (int h = 0; h < 2; h++) {
                    float d = fmaf(-0x1p-11f, C[mt][nt][hf * 2 + h],
                                   xn + env[nt * 2 + h]);
                    int coln = col0 + wn * 64 + nt * 8 + qc * 2 + h;
                    if (d < mv) { mv = d; mi = coln; }
                }
            }
#pragma unroll
            for (int off = 2; off; off >>= 1) {
                float ov = __shfl_down_sync(0xffffffffu, mv, off, 4);
                int   oi = __shfl_down_sync(0xffffffffu, mi, off, 4);
                if (ov < mv || (ov == mv && oi < mi)) { mv = ov; mi = oi; }
            }
            if (qc == 0) {
                unsigned fb = __float_as_uint(mv);
                fb = (fb & 0x80000000u) ? ~fb : (fb | 0x80000000u);
                unsigned long long key =
                    ((unsigned long long)fb << 32) | (unsigned)mi;
                atomicMin(&g_key[row], key);
            }
        }
    }
}

// per-token epilogue: quant_st, per-token loss store, counts, dw scatter
__global__ void k_token(const float* __restrict__ x, const float* __restrict__ emb,
                        float* __restrict__ out) {
    const int t = blockIdx.x;
    const int tid = threadIdx.x;
    const int idx = (int)(g_key[t] & 0xFFFFFFFFULL);
    float4 xv = *(const float4*)(x   + (size_t)t   * DIM + tid * 4);
    float4 qv = *(const float4*)(emb + (size_t)idx * DIM + tid * 4);
    float4 o;
    o.x = xv.x + (qv.x - xv.x);
    o.y = xv.y + (qv.y - xv.y);
    o.z = xv.z + (qv.z - xv.z);
    o.w = xv.w + (qv.w - xv.w);
    *(float4*)(out + O_QUANT + (size_t)t * DIM + tid * 4) = o;
    float ex = xv.x - qv.x, ey = xv.y - qv.y, ez = xv.z - qv.z, ew = xv.w - qv.w;
    float ls = ex * ex + ey * ey + ez * ez + ew * ew;
    float* dwp = g_dw + (size_t)idx * DIM + tid * 4;
    asm volatile("red.global.add.v4.f32 [%0], {%1,%2,%3,%4};"
                 :: "l"(dwp), "f"(xv.x), "f"(xv.y), "f"(xv.z), "f"(xv.w) : "memory");
    for (int off = 16; off; off >>= 1) ls += __shfl_down_sync(0xffffffffu, ls, off);
    __shared__ float ws[4];
    if ((tid & 31) == 0) ws[tid >> 5] = ls;
    __syncthreads();
    if (tid == 0) {
        g_tokloss[t] = ws[0] + ws[1] + ws[2] + ws[3];
        atomicAdd(&g_counts[idx], 1.0f);
        out[O_IDX + t] = (float)idx;
    }
}

__global__ void k_stats(const float* __restrict__ ema_count, float* __restrict__ out) {
    const int t = threadIdx.x;
    const int c0 = 2 * t, c1 = 2 * t + 1;
    const int lane = t & 31, wid = t >> 5;
    float cnt0 = g_counts[c0], cnt1 = g_counts[c1];
    float raw0 = 0.999f * ema_count[c0] + 0.001f * cnt0;
    float raw1 = 0.999f * ema_count[c1] + 0.001f * cnt1;

    // deterministic loss reduction: 32 contiguous partials per thread
    double lsum = 0.0;
#pragma unroll 4
    for (int i = 0; i < 32; i++) lsum += (double)g_tokloss[t * 32 + i];

    double nl = (double)raw0 + (double)raw1;
    for (int off = 16; off; off >>= 1) {
        nl   += __shfl_down_sync(0xffffffffu, nl, off);
        lsum += __shfl_down_sync(0xffffffffu, lsum, off);
    }
    __shared__ double wn[32], wl[32];
    __shared__ float s_n;
    if (lane == 0) { wn[wid] = nl; wl[wid] = lsum; }
    __syncthreads();
    if (t == 0) {
        double s = 0, l = 0;
        for (int i = 0; i < 32; i++) { s += wn[i]; l += wl[i]; }
        s_n = (float)s;
        double m = l * (1.0 / 16777216.0);
        out[O_CODEBK] = (float)m;
        out[O_COMMIT] = (float)(0.25 * m);
    }
    __syncthreads();
    const float n = s_n;
    const float denom = n + 0.02048f;
    float nc0 = ((raw0 + 1e-5f) / denom) * n;
    float nc1 = ((raw1 + 1e-5f) / denom) * n;
    g_newcount[c0] = nc0; g_newcount[c1] = nc1;
    out[O_NEWCNT + c0] = nc0; out[O_NEWCNT + c1] = nc1;

    int f0 = cnt0 > 0.f ? 1 : 0, f1 = cnt1 > 0.f ? 1 : 0;
    int v = f0 + f1;
    int inc = v;
    for (int off = 1; off < 32; off <<= 1) {
        int o = __shfl_up_sync(0xffffffffu, inc, off);
        if (lane >= off) inc += o;
    }
    __shared__ int wsum[32];
    if (lane == 31) wsum[wid] = inc;
    __syncthreads();
    if (wid == 0) {
        int w = wsum[lane];
        for (int off = 1; off < 32; off <<= 1) {
            int o = __shfl_up_sync(0xffffffffu, w, off);
            if (lane >= off) w += o;
        }
        wsum[lane] = w;
    }
    __syncthreads();
    const int total_used = wsum[31];
    int base = (wid > 0 ? wsum[wid - 1] : 0) + (inc - v);
    int p0 = f0 ? base : total_used + (c0 - base);
    int eU1 = base + f0;
    int p1 = f1 ? eU1 : total_used + (c1 - eU1);
    if (p0 < NORTH) { g_sel[p0] = c0; g_valid[p0] = f0 ? 1.0f : 0.0f; }
    if (p1 < NORTH) { g_sel[p1] = c1; g_valid[p1] = f1 ? 1.0f : 0.0f; }
    if (t == 0) {
        g_nvalid = (float)(total_used < NORTH ? total_used : NORTH);
    }
}

__global__ void k_weight(const float* __restrict__ ema_weight, float* __restrict__ out) {
    const int row = blockIdx.x;
    const int tid = threadIdx.x;
    const float nc = g_newcount[row];
    const size_t off = (size_t)row * DIM + tid * 4;
    float4 w  = *(const float4*)(ema_weight + off);
    float4 dv = *(const float4*)(g_dw + off);
    float nw[4], ne[4];
    nw[0] = 0.999f * w.x + 0.001f * dv.x;
    nw[1] = 0.999f * w.y + 0.001f * dv.y;
    nw[2] = 0.999f * w.z + 0.001f * dv.z;
    nw[3] = 0.999f * w.w + 0.001f * dv.w;
#pragma unroll
    for (int u = 0; u < 4; u++) ne[u] = nw[u] / nc;
#pragma unroll
    for (int u = 0; u < 4; u++) {
        out[O_NEWW + off + u]   = nw[u];
        out[O_NEWEMB + off + u] = ne[u];
    }
    *(float4*)(g_newemb + off) = make_float4(ne[0], ne[1], ne[2], ne[3]);
}

__global__ void k_normed() {
    const int r = blockIdx.x;
    const int tid = threadIdx.x;
    const int j = g_sel[r];
    const float valid = g_valid[r];
    float4 v = *(const float4*)(g_newemb + (size_t)j * DIM + tid * 4);
    float ss = v.x * v.x + v.y * v.y + v.z * v.z + v.w * v.w;
    for (int off = 16; off; off >>= 1) ss += __shfl_down_sync(0xffffffffu, ss, off);
    __shared__ float ws[4];
    __shared__ float s_norm;
    if ((tid & 31) == 0) ws[tid >> 5] = ss;
    __syncthreads();
    if (tid == 0) s_norm = fmaxf(sqrtf(ws[0] + ws[1] + ws[2] + ws[3]), 1e-12f);
    __syncthreads();
    const float nrm = s_norm;
    float4 o;
    o.x = v.x / nrm * valid; o.y = v.y / nrm * valid;
    o.z = v.z / nrm * valid; o.w = v.w / nrm * valid;
    *(float4*)(g_normed + (size_t)r * DIM + tid * 4) = o;
}

__global__ void k_cos() {
    const int a = blockIdx.x;
    const int b = threadIdx.x;
    __shared__ float4 sa[128];
    sa[b] = ((const float4*)(g_normed + (size_t)a * DIM))[b];
    __syncthreads();
    const float4* vb = (const float4*)(g_normed + (size_t)b * DIM);
    float dot = 0.f;
#pragma unroll 8
    for (int i = 0; i < 128; i++) {
        float4 pa = sa[i], pb = vb[i];
        dot += pa.x * pb.x + pa.y * pb.y + pa.z * pb.z + pa.w * pb.w;
    }
    float diag = (a == b) ? g_valid[a] : 0.f;
    float d = dot - diag;
    float sq = d * d;
    for (int off = 16; off; off >>= 1) sq += __shfl_down_sync(0xffffffffu, sq, off);
    __shared__ float ws[4];
    if ((b & 31) == 0) ws[b >> 5] = sq;
    __syncthreads();
    if (b == 0) atomicAdd(&g_scal[1], (double)(ws[0] + ws[1] + ws[2] + ws[3]));
}

__global__ void k_ortho(float* __restrict__ out) {
    float nv = g_nvalid;
    out[O_ORTHO] = (float)(g_scal[1] / ((double)nv * (double)nv) * 10.0);
}

extern "C" void kernel_launch(void* const* d_in, const int* in_sizes, int n_in,
                              void* d_out, int out_size) {
    const float* x          = (const float*)d_in[0];
    const float* emb        = (const float*)d_in[1];
    const float* ema_count  = (const float*)d_in[2];
    const float* ema_weight = (const float*)d_in[3];
    float* out = (float*)d_out;

    cudaFuncSetAttribute(k_mma, cudaFuncAttributeMaxDynamicSharedMemorySize,
                         2 * STAGEB);

    k_pad<<<1, 32>>>();                           // #1
    k_pad<<<1, 32>>>();                           // #2
    k_pad<<<1, 32>>>();                           // #3
    k_prep<<<4352, 256>>>(x, emb);                // #4 (profiled this round)
    k_mma<<<dim3(16, 256), 256, 2 * STAGEB>>>();
    k_token<<<NTOK, 128>>>(x, emb, out);
    k_stats<<<1, 1024>>>(ema_count, out);
    k_weight<<<MCODE, 128>>>(ema_weight, out);
    k_normed<<<NORTH, 128>>>();
    k_cos<<<NORTH, 128>>>();
    k_ortho<<<1, 1>>>(out);
}